// round 12
// baseline (speedup 1.0000x reference)
#include <cuda_runtime.h>

#define BB 4
#define KK 128
#define NPTS 50000
#define GD 128
#define TPB 128
#define PPB 256                           // points per block (2 per thread)
#define CHUNKS ((NPTS + PPB - 1) / PPB)   // 196
#define NBLK (CHUNKS * BB)                // 784

typedef unsigned long long u64;

__device__ float        g_partials[NBLK];
__device__ unsigned int g_count = 0;

// ---- packed f32x2 helpers ----
__device__ __forceinline__ u64 pk2(float lo, float hi) {
    u64 r; asm("mov.b64 %0, {%1, %2};" : "=l"(r) : "f"(lo), "f"(hi)); return r;
}
__device__ __forceinline__ void upk2(float& lo, float& hi, u64 v) {
    asm("mov.b64 {%0, %1}, %2;" : "=f"(lo), "=f"(hi) : "l"(v));
}
#define F2FMA(d,a,b,c) asm("fma.rn.f32x2 %0, %1, %2, %3;" : "=l"(d) : "l"(a), "l"(b), "l"(c))
#define F2ADD(d,a,b)   asm("add.rn.f32x2 %0, %1, %2;"     : "=l"(d) : "l"(a), "l"(b))
#define F2MUL(d,a,b)   asm("mul.rn.f32x2 %0, %1, %2;"     : "=l"(d) : "l"(a), "l"(b))

__device__ __forceinline__ float ex2f(float x) {
    float r; asm("ex2.approx.ftz.f32 %0, %1;" : "=f"(r) : "f"(x)); return r;
}

// world -> grid -> normalized -> grid round trip + trilinear border sample
__device__ __forceinline__ float sample_sdf(const float* __restrict__ vol,
                                            const float* __restrict__ A,
                                            float bx, float by, float bz)
{
    float gx = __ldg(A + 0) * bx + __ldg(A + 1) * by + __ldg(A + 2)  * bz + __ldg(A + 3);
    float gy = __ldg(A + 4) * bx + __ldg(A + 5) * by + __ldg(A + 6)  * bz + __ldg(A + 7);
    float gz = __ldg(A + 8) * bx + __ldg(A + 9) * by + __ldg(A + 10) * bz + __ldg(A + 11);

    const float dm = (float)(GD - 1);
    float ncx = 2.0f * (gx / dm) - 1.0f;
    float ncy = 2.0f * (gy / dm) - 1.0f;
    float ncz = 2.0f * (gz / dm) - 1.0f;

    float x = fminf(fmaxf((ncx + 1.0f) * 0.5f * dm, 0.0f), dm);
    float y = fminf(fmaxf((ncy + 1.0f) * 0.5f * dm, 0.0f), dm);
    float z = fminf(fmaxf((ncz + 1.0f) * 0.5f * dm, 0.0f), dm);

    float x0f = floorf(x), y0f = floorf(y), z0f = floorf(z);
    float fx = x - x0f, fy = y - y0f, fz = z - z0f;
    int x0 = (int)x0f, y0 = (int)y0f, z0 = (int)z0f;
    int x1 = min(x0 + 1, GD - 1);
    int y1 = min(y0 + 1, GD - 1);
    int z1 = min(z0 + 1, GD - 1);

    const int sz = GD * GD;
    int b00 = z0 * sz + y0 * GD;
    int b01 = z0 * sz + y1 * GD;
    int b10 = z1 * sz + y0 * GD;
    int b11 = z1 * sz + y1 * GD;

    float c000 = __ldg(vol + b00 + x0);
    float c001 = __ldg(vol + b00 + x1);
    float c010 = __ldg(vol + b01 + x0);
    float c011 = __ldg(vol + b01 + x1);
    float c100 = __ldg(vol + b10 + x0);
    float c101 = __ldg(vol + b10 + x1);
    float c110 = __ldg(vol + b11 + x0);
    float c111 = __ldg(vol + b11 + x1);

    float c00 = c000 + (c001 - c000) * fx;
    float c01 = c010 + (c011 - c010) * fx;
    float c10 = c100 + (c101 - c100) * fx;
    float c11 = c110 + (c111 - c110) * fx;
    float c0  = c00 + (c01 - c00) * fy;
    float c1  = c10 + (c11 - c10) * fy;
    return c0 + (c1 - c0) * fz;
}

// One packed (2-point) gaussian step into the given accumulator set.
__device__ __forceinline__ void gauss_step(
    const ulonglong2* __restrict__ sq,
    u64 pxp, u64 pyp, u64 pzp,
    u64& ax, u64& ay, u64& az, u64& ws)
{
    const ulonglong2 j0 = sq[0];   // (-cx,-cy)
    const ulonglong2 j1 = sq[1];   // (-cz, ni)
    u64 dx; F2ADD(dx, pxp, j0.x);
    u64 dy; F2ADD(dy, pyp, j0.y);
    u64 dz; F2ADD(dz, pzp, j1.x);

    u64 t;  F2MUL(t, dz, dz);
    F2FMA(t, dy, dy, t);
    F2FMA(t, dx, dx, t);

    const ulonglong2 j2 = sq[2];   // (lc, r00)
    u64 arg; F2FMA(arg, t, j1.y, j2.x);
    float a0, a1; upk2(a0, a1, arg);
    const u64 w = pk2(ex2f(a0), ex2f(a1));

    const ulonglong2 j3 = sq[3];   // (r01, r02)
    const ulonglong2 j4 = sq[4];   // (r10, r11)
    const ulonglong2 j5 = sq[5];   // (r12, r20)
    const ulonglong2 j6 = sq[6];   // (r21, r22)
    const ulonglong2 j7 = sq[7];   // (ctx, cty)
    const ulonglong2 j8 = sq[8];   // (ctz, pad)

    u64 tx; F2FMA(tx, j3.y, dz, j7.x);
    F2FMA(tx, j3.x, dy, tx);
    F2FMA(tx, j2.y, dx, tx);

    u64 ty; F2FMA(ty, j5.x, dz, j7.y);
    F2FMA(ty, j4.y, dy, ty);
    F2FMA(ty, j4.x, dx, ty);

    u64 tz; F2FMA(tz, j6.y, dz, j8.x);
    F2FMA(tz, j6.x, dy, tz);
    F2FMA(tz, j5.y, dx, tz);

    F2FMA(ax, w, tx, ax);
    F2FMA(ay, w, ty, ay);
    F2FMA(az, w, tz, az);
    F2ADD(ws, ws, w);
}

// Per-k duplicated param layout (18 u64 = 144B, 16B aligned):
//  j0=(-cx,-cy) j1=(-cz,ni) j2=(lc,r00) j3=(r01,r02) j4=(r10,r11)
//  j5=(r12,r20) j6=(r21,r22) j7=(ctx,cty) j8=(ctz,pad)   [each u64 = (v,v)]
__global__ __launch_bounds__(TPB) void fused_kernel(
    const float* __restrict__ constants,
    const float* __restrict__ scales,
    const float* __restrict__ rotations,
    const float* __restrict__ centers,
    const float* __restrict__ samples,
    const float* __restrict__ grid,
    const float* __restrict__ w2g,
    float* __restrict__ out)
{
    __shared__ __align__(16) u64 sParams[KK * 18];
    __shared__ float sRed[TPB / 32];
    __shared__ int   sLast;

    const int b     = blockIdx.y;
    const int bn    = (b + 1) % BB;
    const int chunk = blockIdx.x;
    const int tid   = threadIdx.x;

    // ---- prologue: per-block param precompute (one k per thread; TPB==KK) ----
    {
        const int k = tid;
        float R[3][3], Rn[3][3];
        const float* rp  = rotations + ((size_t)b  * KK + k) * 9;
        const float* rpn = rotations + ((size_t)bn * KK + k) * 9;
#pragma unroll
        for (int i = 0; i < 3; i++)
#pragma unroll
            for (int j = 0; j < 3; j++) {
                R[i][j]  = __ldg(rp  + i * 3 + j);
                Rn[i][j] = __ldg(rpn + i * 3 + j);
            }
        float Rr[3][3];
#pragma unroll
        for (int i = 0; i < 3; i++)
#pragma unroll
            for (int l = 0; l < 3; l++)
                Rr[i][l] = Rn[i][0] * R[l][0] + Rn[i][1] * R[l][1] + Rn[i][2] * R[l][2];

        const float cx  = __ldg(centers + ((size_t)b  * KK + k) * 3 + 0);
        const float cy  = __ldg(centers + ((size_t)b  * KK + k) * 3 + 1);
        const float cz  = __ldg(centers + ((size_t)b  * KK + k) * 3 + 2);
        const float ctx = __ldg(centers + ((size_t)bn * KK + k) * 3 + 0);
        const float cty = __ldg(centers + ((size_t)bn * KK + k) * 3 + 1);
        const float ctz = __ldg(centers + ((size_t)bn * KK + k) * 3 + 2);

        const float s = __ldg(scales    + (size_t)b * KK + k);
        const float c = __ldg(constants + (size_t)b * KK + k);
        const float LOG2E = 1.4426950408889634f;
        const float ni = -(1.0f / (2.0f * s * s)) * LOG2E;   // ex2 domain
        const float lc = __log2f(c * c);                      // log2(c^2)

        u64* d = sParams + k * 18;
        d[0]  = pk2(-cx, -cx);
        d[1]  = pk2(-cy, -cy);
        d[2]  = pk2(-cz, -cz);
        d[3]  = pk2(ni, ni);
        d[4]  = pk2(lc, lc);
        d[5]  = pk2(Rr[0][0], Rr[0][0]);
        d[6]  = pk2(Rr[0][1], Rr[0][1]);
        d[7]  = pk2(Rr[0][2], Rr[0][2]);
        d[8]  = pk2(Rr[1][0], Rr[1][0]);
        d[9]  = pk2(Rr[1][1], Rr[1][1]);
        d[10] = pk2(Rr[1][2], Rr[1][2]);
        d[11] = pk2(Rr[2][0], Rr[2][0]);
        d[12] = pk2(Rr[2][1], Rr[2][1]);
        d[13] = pk2(Rr[2][2], Rr[2][2]);
        d[14] = pk2(ctx, ctx);
        d[15] = pk2(cty, cty);
        d[16] = pk2(ctz, ctz);
        d[17] = 0ULL;
    }
    __syncthreads();

    // ---- load the two points of this thread (tail-guarded) ----
    const int n0 = chunk * PPB + tid;
    const int n1 = n0 + TPB;
    const bool v0 = (n0 < NPTS);
    const bool v1 = (n1 < NPTS);
    const int m0 = v0 ? n0 : (NPTS - 1);
    const int m1 = v1 ? n1 : (NPTS - 1);

    const float* base = samples + (size_t)b * NPTS * 6;
    const float px0 = base[m0 * 6 + 0], py0 = base[m0 * 6 + 1], pz0 = base[m0 * 6 + 2];
    const float px1 = base[m1 * 6 + 0], py1 = base[m1 * 6 + 1], pz1 = base[m1 * 6 + 2];

    const u64 pxp = pk2(px0, px1);
    const u64 pyp = pk2(py0, py1);
    const u64 pzp = pk2(pz0, pz1);

    // Two independent accumulator sets (even/odd k) to break the RAW chain
    u64 axE = 0ULL, ayE = 0ULL, azE = 0ULL, wsE = 0ULL;
    u64 axO = 0ULL, ayO = 0ULL, azO = 0ULL, wsO = 0ULL;

    const ulonglong2* __restrict__ sq = (const ulonglong2*)sParams;

    // ---- main loop: 2 gaussians per iteration, independent accumulators ----
#pragma unroll 2
    for (int k = 0; k < KK; k += 2) {
        gauss_step(sq,     pxp, pyp, pzp, axE, ayE, azE, wsE);
        gauss_step(sq + 9, pxp, pyp, pzp, axO, ayO, azO, wsO);
        sq += 18;
    }

    u64 ax; F2ADD(ax, axE, axO);
    u64 ay; F2ADD(ay, ayE, ayO);
    u64 az; F2ADD(az, azE, azO);
    u64 ws; F2ADD(ws, wsE, wsO);

    // ---- epilogue: normalize, transform, trilinear sample, square ----
    const float* A   = w2g + (size_t)bn * 16;
    const float* vol = grid + (size_t)bn * GD * GD * GD;

    float x0, x1, y0, y1, z0, z1, w0, w1;
    upk2(x0, x1, ax); upk2(y0, y1, ay); upk2(z0, z1, az); upk2(w0, w1, ws);

    float local = 0.0f;
    if (v0) {
        const float inv = 1.0f / w0;
        const float s0 = sample_sdf(vol, A, x0 * inv, y0 * inv, z0 * inv);
        local += s0 * s0;
    }
    if (v1) {
        const float inv = 1.0f / w1;
        const float s1 = sample_sdf(vol, A, x1 * inv, y1 * inv, z1 * inv);
        local += s1 * s1;
    }

    // ---- block reduction (deterministic) ----
    float v = local;
#pragma unroll
    for (int off = 16; off > 0; off >>= 1)
        v += __shfl_down_sync(0xFFFFFFFFu, v, off);
    const int lane = tid & 31;
    const int warp = tid >> 5;
    if (lane == 0) sRed[warp] = v;
    __syncthreads();
    if (warp == 0) {
        v = (lane < TPB / 32) ? sRed[lane] : 0.0f;
#pragma unroll
        for (int off = 2; off > 0; off >>= 1)
            v += __shfl_down_sync(0xFFFFFFFFu, v, off);
        if (lane == 0) g_partials[b * CHUNKS + chunk] = v;
    }
    __syncthreads();

    // ---- last block reduces all partials (graph-replay-safe counter) ----
    if (tid == 0) {
        __threadfence();
        unsigned int prev = atomicAdd(&g_count, 1u);
        sLast = (prev == (unsigned int)(NBLK - 1)) ? 1 : 0;
    }
    __syncthreads();

    if (sLast) {
        float r = 0.0f;
        for (int i = tid; i < NBLK; i += TPB) r += g_partials[i];
#pragma unroll
        for (int off = 16; off > 0; off >>= 1)
            r += __shfl_down_sync(0xFFFFFFFFu, r, off);
        if (lane == 0) sRed[warp] = r;
        __syncthreads();
        if (warp == 0) {
            r = (lane < TPB / 32) ? sRed[lane] : 0.0f;
#pragma unroll
            for (int off = 2; off > 0; off >>= 1)
                r += __shfl_down_sync(0xFFFFFFFFu, r, off);
            if (lane == 0) {
                out[0] = r / (float)NPTS;
                g_count = 0u;   // self-reset for next graph replay
            }
        }
    }
}

extern "C" void kernel_launch(void* const* d_in, const int* in_sizes, int n_in,
                              void* d_out, int out_size)
{
    const float* constants = (const float*)d_in[0]; // (B,K)
    const float* scales    = (const float*)d_in[1]; // (B,K)
    const float* rotations = (const float*)d_in[2]; // (B,K,3,3)
    const float* centers   = (const float*)d_in[3]; // (B,K,3)
    const float* samples   = (const float*)d_in[4]; // (B,N,6)
    const float* grid      = (const float*)d_in[5]; // (B,GD,GD,GD)
    const float* w2g       = (const float*)d_in[6]; // (B,4,4)
    float* out = (float*)d_out;

    dim3 g(CHUNKS, BB);
    fused_kernel<<<g, TPB>>>(constants, scales, rotations, centers,
                             samples, grid, w2g, out);
}

// round 15
// speedup vs baseline: 1.1557x; 1.1557x over previous
#include <cuda_runtime.h>

#define BB 4
#define KK 128
#define HK 64                              // k's per half
#define NPTS 50000
#define GD 128

#define TPB1 128
#define PPB1 1024                          // 8 points per thread
#define CH1 ((NPTS + PPB1 - 1) / PPB1)     // 49
#define NPAD (CH1 * PPB1)                  // 50176

#define TPB2 256
#define CH2 ((NPTS + TPB2 - 1) / TPB2)     // 196
#define NBLK2 (CH2 * BB)                   // 784

typedef unsigned long long u64;

__device__ float4       g_part[2 * BB * NPAD];   // (half, b, n) partial (ax,ay,az,ws)
__device__ float        g_partials[NBLK2];
__device__ unsigned int g_count = 0;

// ---- packed f32x2 helpers ----
__device__ __forceinline__ u64 pk2(float lo, float hi) {
    u64 r; asm("mov.b64 %0, {%1, %2};" : "=l"(r) : "f"(lo), "f"(hi)); return r;
}
__device__ __forceinline__ void upk2(float& lo, float& hi, u64 v) {
    asm("mov.b64 {%0, %1}, %2;" : "=f"(lo), "=f"(hi) : "l"(v));
}
#define F2FMA(d,a,b,c) asm("fma.rn.f32x2 %0, %1, %2, %3;" : "=l"(d) : "l"(a), "l"(b), "l"(c))
#define F2ADD(d,a,b)   asm("add.rn.f32x2 %0, %1, %2;"     : "=l"(d) : "l"(a), "l"(b))
#define F2MUL(d,a,b)   asm("mul.rn.f32x2 %0, %1, %2;"     : "=l"(d) : "l"(a), "l"(b))

__device__ __forceinline__ float ex2f(float x) {
    float r; asm("ex2.approx.ftz.f32 %0, %1;" : "=f"(r) : "f"(x)); return r;
}

// One packed (2-point) gaussian step into the given accumulator set.
__device__ __forceinline__ void gauss_step(
    const ulonglong2 j0, const ulonglong2 j1, const ulonglong2 j2,
    const ulonglong2 j3, const ulonglong2 j4, const ulonglong2 j5,
    const ulonglong2 j6, const ulonglong2 j7, const ulonglong2 j8,
    u64 pxp, u64 pyp, u64 pzp,
    u64& ax, u64& ay, u64& az, u64& ws)
{
    u64 dx; F2ADD(dx, pxp, j0.x);
    u64 dy; F2ADD(dy, pyp, j0.y);
    u64 dz; F2ADD(dz, pzp, j1.x);

    u64 t;  F2MUL(t, dz, dz);
    F2FMA(t, dy, dy, t);
    F2FMA(t, dx, dx, t);

    u64 arg; F2FMA(arg, t, j1.y, j2.x);
    float a0, a1; upk2(a0, a1, arg);
    const u64 w = pk2(ex2f(a0), ex2f(a1));

    u64 tx; F2FMA(tx, j3.y, dz, j7.x);
    F2FMA(tx, j3.x, dy, tx);
    F2FMA(tx, j2.y, dx, tx);

    u64 ty; F2FMA(ty, j5.x, dz, j7.y);
    F2FMA(ty, j4.y, dy, ty);
    F2FMA(ty, j4.x, dx, ty);

    u64 tz; F2FMA(tz, j6.y, dz, j8.x);
    F2FMA(tz, j6.x, dy, tz);
    F2FMA(tz, j5.y, dx, tz);

    F2FMA(ax, w, tx, ax);
    F2FMA(ay, w, ty, ay);
    F2FMA(az, w, tz, az);
    F2ADD(ws, ws, w);
}

// =====================  PHASE 1: gaussian accumulation  =====================
// grid = (CH1, BB, 2). Each block: 1024 points x 64 gaussians (one K-half).
// Per-k duplicated param layout in smem (18 u64 = 144B):
//  j0=(-cx,-cy) j1=(-cz,ni) j2=(lc,r00) j3=(r01,r02) j4=(r10,r11)
//  j5=(r12,r20) j6=(r21,r22) j7=(ctx,cty) j8=(ctz,pad)  [each u64 = (v,v)]
__global__ __launch_bounds__(TPB1) void phase1_kernel(
    const float* __restrict__ constants,
    const float* __restrict__ scales,
    const float* __restrict__ rotations,
    const float* __restrict__ centers,
    const float* __restrict__ samples)
{
    __shared__ __align__(16) u64 sParams[HK * 18];

    const int b     = blockIdx.y;
    const int bn    = (b + 1) % BB;
    const int half  = blockIdx.z;
    const int chunk = blockIdx.x;
    const int tid   = threadIdx.x;

    // ---- prologue: params for this K-half (threads 0..63, one k each) ----
    if (tid < HK) {
        const int k = half * HK + tid;
        float R[3][3], Rn[3][3];
        const float* rp  = rotations + ((size_t)b  * KK + k) * 9;
        const float* rpn = rotations + ((size_t)bn * KK + k) * 9;
#pragma unroll
        for (int i = 0; i < 3; i++)
#pragma unroll
            for (int j = 0; j < 3; j++) {
                R[i][j]  = __ldg(rp  + i * 3 + j);
                Rn[i][j] = __ldg(rpn + i * 3 + j);
            }
        float Rr[3][3];
#pragma unroll
        for (int i = 0; i < 3; i++)
#pragma unroll
            for (int l = 0; l < 3; l++)
                Rr[i][l] = Rn[i][0] * R[l][0] + Rn[i][1] * R[l][1] + Rn[i][2] * R[l][2];

        const float cx  = __ldg(centers + ((size_t)b  * KK + k) * 3 + 0);
        const float cy  = __ldg(centers + ((size_t)b  * KK + k) * 3 + 1);
        const float cz  = __ldg(centers + ((size_t)b  * KK + k) * 3 + 2);
        const float ctx = __ldg(centers + ((size_t)bn * KK + k) * 3 + 0);
        const float cty = __ldg(centers + ((size_t)bn * KK + k) * 3 + 1);
        const float ctz = __ldg(centers + ((size_t)bn * KK + k) * 3 + 2);

        const float s = __ldg(scales    + (size_t)b * KK + k);
        const float c = __ldg(constants + (size_t)b * KK + k);
        const float LOG2E = 1.4426950408889634f;
        const float ni = -(1.0f / (2.0f * s * s)) * LOG2E;   // ex2 domain
        const float lc = __log2f(c * c);                      // log2(c^2)

        u64* d = sParams + tid * 18;
        d[0]  = pk2(-cx, -cx);
        d[1]  = pk2(-cy, -cy);
        d[2]  = pk2(-cz, -cz);
        d[3]  = pk2(ni, ni);
        d[4]  = pk2(lc, lc);
        d[5]  = pk2(Rr[0][0], Rr[0][0]);
        d[6]  = pk2(Rr[0][1], Rr[0][1]);
        d[7]  = pk2(Rr[0][2], Rr[0][2]);
        d[8]  = pk2(Rr[1][0], Rr[1][0]);
        d[9]  = pk2(Rr[1][1], Rr[1][1]);
        d[10] = pk2(Rr[1][2], Rr[1][2]);
        d[11] = pk2(Rr[2][0], Rr[2][0]);
        d[12] = pk2(Rr[2][1], Rr[2][1]);
        d[13] = pk2(Rr[2][2], Rr[2][2]);
        d[14] = pk2(ctx, ctx);
        d[15] = pk2(cty, cty);
        d[16] = pk2(ctz, ctz);
        d[17] = 0ULL;
    }
    __syncthreads();

    // ---- 8 points of this thread (clamped loads; guarded stores) ----
    const int nb = chunk * PPB1 + tid;
    const float* base = samples + (size_t)b * NPTS * 6;

    float px[8], py[8], pz[8];
    int   nn[8];
#pragma unroll
    for (int i = 0; i < 8; i++) {
        int n = nb + i * TPB1;
        nn[i] = n;
        int m = (n < NPTS) ? n : (NPTS - 1);
        px[i] = base[m * 6 + 0];
        py[i] = base[m * 6 + 1];
        pz[i] = base[m * 6 + 2];
    }

    const u64 pxA = pk2(px[0], px[1]), pyA = pk2(py[0], py[1]), pzA = pk2(pz[0], pz[1]);
    const u64 pxB = pk2(px[2], px[3]), pyB = pk2(py[2], py[3]), pzB = pk2(pz[2], pz[3]);
    const u64 pxC = pk2(px[4], px[5]), pyC = pk2(py[4], py[5]), pzC = pk2(pz[4], pz[5]);
    const u64 pxD = pk2(px[6], px[7]), pyD = pk2(py[6], py[7]), pzD = pk2(pz[6], pz[7]);

    u64 axA = 0ULL, ayA = 0ULL, azA = 0ULL, wsA = 0ULL;
    u64 axB = 0ULL, ayB = 0ULL, azB = 0ULL, wsB = 0ULL;
    u64 axC = 0ULL, ayC = 0ULL, azC = 0ULL, wsC = 0ULL;
    u64 axD = 0ULL, ayD = 0ULL, azD = 0ULL, wsD = 0ULL;

    const ulonglong2* __restrict__ sq = (const ulonglong2*)sParams;

    // ---- main loop: 64 gaussians, each param load feeds 8 points ----
#pragma unroll 2
    for (int k = 0; k < HK; k++) {
        const ulonglong2 j0 = sq[0];
        const ulonglong2 j1 = sq[1];
        const ulonglong2 j2 = sq[2];
        const ulonglong2 j3 = sq[3];
        const ulonglong2 j4 = sq[4];
        const ulonglong2 j5 = sq[5];
        const ulonglong2 j6 = sq[6];
        const ulonglong2 j7 = sq[7];
        const ulonglong2 j8 = sq[8];

        gauss_step(j0,j1,j2,j3,j4,j5,j6,j7,j8, pxA,pyA,pzA, axA,ayA,azA,wsA);
        gauss_step(j0,j1,j2,j3,j4,j5,j6,j7,j8, pxB,pyB,pzB, axB,ayB,azB,wsB);
        gauss_step(j0,j1,j2,j3,j4,j5,j6,j7,j8, pxC,pyC,pzC, axC,ayC,azC,wsC);
        gauss_step(j0,j1,j2,j3,j4,j5,j6,j7,j8, pxD,pyD,pzD, axD,ayD,azD,wsD);

        sq += 9;
    }

    // ---- write per-point partials (coalesced float4 stores) ----
    float4* dst = g_part + (size_t)(half * BB + b) * NPAD;

    float x0, x1, y0, y1, z0, z1, w0, w1;
    upk2(x0, x1, axA); upk2(y0, y1, ayA); upk2(z0, z1, azA); upk2(w0, w1, wsA);
    if (nn[0] < NPTS) dst[nn[0]] = make_float4(x0, y0, z0, w0);
    if (nn[1] < NPTS) dst[nn[1]] = make_float4(x1, y1, z1, w1);
    upk2(x0, x1, axB); upk2(y0, y1, ayB); upk2(z0, z1, azB); upk2(w0, w1, wsB);
    if (nn[2] < NPTS) dst[nn[2]] = make_float4(x0, y0, z0, w0);
    if (nn[3] < NPTS) dst[nn[3]] = make_float4(x1, y1, z1, w1);
    upk2(x0, x1, axC); upk2(y0, y1, ayC); upk2(z0, z1, azC); upk2(w0, w1, wsC);
    if (nn[4] < NPTS) dst[nn[4]] = make_float4(x0, y0, z0, w0);
    if (nn[5] < NPTS) dst[nn[5]] = make_float4(x1, y1, z1, w1);
    upk2(x0, x1, axD); upk2(y0, y1, ayD); upk2(z0, z1, azD); upk2(w0, w1, wsD);
    if (nn[6] < NPTS) dst[nn[6]] = make_float4(x0, y0, z0, w0);
    if (nn[7] < NPTS) dst[nn[7]] = make_float4(x1, y1, z1, w1);
}

// =====================  PHASE 2: combine + sample + reduce  =====================
__device__ __forceinline__ float sample_sdf(const float* __restrict__ vol,
                                            const float* __restrict__ A,
                                            float bx, float by, float bz)
{
    float gx = __ldg(A + 0) * bx + __ldg(A + 1) * by + __ldg(A + 2)  * bz + __ldg(A + 3);
    float gy = __ldg(A + 4) * bx + __ldg(A + 5) * by + __ldg(A + 6)  * bz + __ldg(A + 7);
    float gz = __ldg(A + 8) * bx + __ldg(A + 9) * by + __ldg(A + 10) * bz + __ldg(A + 11);

    const float dm = (float)(GD - 1);
    float ncx = 2.0f * (gx / dm) - 1.0f;
    float ncy = 2.0f * (gy / dm) - 1.0f;
    float ncz = 2.0f * (gz / dm) - 1.0f;

    float x = fminf(fmaxf((ncx + 1.0f) * 0.5f * dm, 0.0f), dm);
    float y = fminf(fmaxf((ncy + 1.0f) * 0.5f * dm, 0.0f), dm);
    float z = fminf(fmaxf((ncz + 1.0f) * 0.5f * dm, 0.0f), dm);

    float x0f = floorf(x), y0f = floorf(y), z0f = floorf(z);
    float fx = x - x0f, fy = y - y0f, fz = z - z0f;
    int x0 = (int)x0f, y0 = (int)y0f, z0 = (int)z0f;
    int x1 = min(x0 + 1, GD - 1);
    int y1 = min(y0 + 1, GD - 1);
    int z1 = min(z0 + 1, GD - 1);

    const int sz = GD * GD;
    int b00 = z0 * sz + y0 * GD;
    int b01 = z0 * sz + y1 * GD;
    int b10 = z1 * sz + y0 * GD;
    int b11 = z1 * sz + y1 * GD;

    float c000 = __ldg(vol + b00 + x0);
    float c001 = __ldg(vol + b00 + x1);
    float c010 = __ldg(vol + b01 + x0);
    float c011 = __ldg(vol + b01 + x1);
    float c100 = __ldg(vol + b10 + x0);
    float c101 = __ldg(vol + b10 + x1);
    float c110 = __ldg(vol + b11 + x0);
    float c111 = __ldg(vol + b11 + x1);

    float c00 = c000 + (c001 - c000) * fx;
    float c01 = c010 + (c011 - c010) * fx;
    float c10 = c100 + (c101 - c100) * fx;
    float c11 = c110 + (c111 - c110) * fx;
    float c0  = c00 + (c01 - c00) * fy;
    float c1  = c10 + (c11 - c10) * fy;
    return c0 + (c1 - c0) * fz;
}

__global__ __launch_bounds__(TPB2) void phase2_kernel(
    const float* __restrict__ grid,
    const float* __restrict__ w2g,
    float* __restrict__ out)
{
    __shared__ float sRed[TPB2 / 32];
    __shared__ int   sLast;

    const int b   = blockIdx.y;
    const int bn  = (b + 1) % BB;
    const int tid = threadIdx.x;
    const int n   = blockIdx.x * TPB2 + tid;

    const float* A   = w2g + (size_t)bn * 16;
    const float* vol = grid + (size_t)bn * GD * GD * GD;

    float local = 0.0f;
    if (n < NPTS) {
        const float4 h0 = g_part[(size_t)(0 * BB + b) * NPAD + n];
        const float4 h1 = g_part[(size_t)(1 * BB + b) * NPAD + n];
        const float ws = h0.w + h1.w;
        const float inv = 1.0f / ws;
        const float bx = (h0.x + h1.x) * inv;
        const float by = (h0.y + h1.y) * inv;
        const float bz = (h0.z + h1.z) * inv;
        const float s = sample_sdf(vol, A, bx, by, bz);
        local = s * s;
    }

    // ---- block reduction (deterministic) ----
    float v = local;
#pragma unroll
    for (int off = 16; off > 0; off >>= 1)
        v += __shfl_down_sync(0xFFFFFFFFu, v, off);
    const int lane = tid & 31;
    const int warp = tid >> 5;
    if (lane == 0) sRed[warp] = v;
    __syncthreads();
    if (warp == 0) {
        v = (lane < TPB2 / 32) ? sRed[lane] : 0.0f;
#pragma unroll
        for (int off = 4; off > 0; off >>= 1)
            v += __shfl_down_sync(0xFFFFFFFFu, v, off);
        if (lane == 0) g_partials[b * CH2 + blockIdx.x] = v;
    }
    __syncthreads();

    // ---- last block reduces all partials (graph-replay-safe counter) ----
    if (tid == 0) {
        __threadfence();
        unsigned int prev = atomicAdd(&g_count, 1u);
        sLast = (prev == (unsigned int)(NBLK2 - 1)) ? 1 : 0;
    }
    __syncthreads();

    if (sLast) {
        float r = 0.0f;
        for (int i = tid; i < NBLK2; i += TPB2) r += g_partials[i];
#pragma unroll
        for (int off = 16; off > 0; off >>= 1)
            r += __shfl_down_sync(0xFFFFFFFFu, r, off);
        if (lane == 0) sRed[warp] = r;
        __syncthreads();
        if (warp == 0) {
            r = (lane < TPB2 / 32) ? sRed[lane] : 0.0f;
#pragma unroll
            for (int off = 4; off > 0; off >>= 1)
                r += __shfl_down_sync(0xFFFFFFFFu, r, off);
            if (lane == 0) {
                out[0] = r / (float)NPTS;
                g_count = 0u;   // self-reset for next graph replay
            }
        }
    }
}

extern "C" void kernel_launch(void* const* d_in, const int* in_sizes, int n_in,
                              void* d_out, int out_size)
{
    const float* constants = (const float*)d_in[0]; // (B,K)
    const float* scales    = (const float*)d_in[1]; // (B,K)
    const float* rotations = (const float*)d_in[2]; // (B,K,3,3)
    const float* centers   = (const float*)d_in[3]; // (B,K,3)
    const float* samples   = (const float*)d_in[4]; // (B,N,6)
    const float* grid      = (const float*)d_in[5]; // (B,GD,GD,GD)
    const float* w2g       = (const float*)d_in[6]; // (B,4,4)
    float* out = (float*)d_out;

    dim3 g1(CH1, BB, 2);
    phase1_kernel<<<g1, TPB1>>>(constants, scales, rotations, centers, samples);
    dim3 g2(CH2, BB);
    phase2_kernel<<<g2, TPB2>>>(grid, w2g, out);
}